// round 11
// baseline (speedup 1.0000x reference)
#include <cuda_runtime.h>

// LDM Kalman forward, 256 seq x 1024 steps, 5 launches:
//   k_scan     : per-CTA mask==1 flags into g_bad
//   k1_riccati : shared Riccati to steady state (1 CTA), single inversion/step
//                Lam=(I+PS)^-1 P, G=I-Lam S, M=A-T S (12 syncs/step)
//   k2_dfl     : 64 t/CTA; d=N a+B u, f=K a; streams all Lambda outputs
//   k3_mu      : affine mu recursion, 16 chunks of 64/seq with 64-step burn-in,
//                8-deep prefetch (16 shfl+16 FMA per step)
//   fallback   : full general-mask kernel (guarded)

#define T_STEPS 1024
#define NB 256
#define DX 16
#define DA 32
#define TC 192

#define BASE_MP 0ul
#define BASE_MT 4194304ul
#define BASE_LP 8388608ul
#define BASE_LT 75497472ul

__device__ int g_allones;
__device__ int g_tc;
__device__ int g_bad[1024];
__device__ float g_Mt[TC][DX][17];
__device__ float g_Gt[TC][DX][17];
__device__ float g_Nt[TC][DX][33];
__device__ float g_Kt[TC][DX][33];
__device__ __align__(16) float g_Lp[TC][256];
__device__ __align__(16) float g_Lt[TC][256];
__device__ float g_df[2][NB][T_STEPS][DX];

__device__ __forceinline__ float frcp_acc(float x) {
    float r;
    asm("rcp.approx.f32 %0, %1;" : "=f"(r) : "f"(x));
    float e = __fmaf_rn(-x, r, 1.0f);
    r = __fmaf_rn(r, e, r);
    return r;
}

__device__ __forceinline__ float gj_stage(float (*M)[17], float (*rb)[2][DX],
                                          float (*cb)[2][DX], float (*spv)[4],
                                          int i, int j, int s) {
    const int par = s & 1;
    const int k0 = 2 * s, k1 = 2 * s + 1;
    const float p00 = spv[par][0], p01 = spv[par][1];
    const float p10 = spv[par][2], p11 = spv[par][3];
    const float rd = frcp_acc(__fmaf_rn(p00, p11, -(p01 * p10)));
    const float q00 = p11 * rd, q01 = -p01 * rd;
    const float q10 = -p10 * rd, q11 = p00 * rd;
    const float r0 = rb[par][0][j], r1 = rb[par][1][j];
    const float c0 = cb[par][0][i], c1 = cb[par][1][i];
    const float v = M[i][j];
    const float w0 = __fmaf_rn(q00, r0, q01 * r1);
    const float w1 = __fmaf_rn(q10, r0, q11 * r1);
    const bool ip = (i == k0) || (i == k1);
    const bool jp = (j == k0) || (j == k1);
    float nv;
    if (ip && jp)      nv = (i == k0) ? ((j == k0) ? q00 : q01)
                                      : ((j == k0) ? q10 : q11);
    else if (ip)       nv = (i == k0) ? w0 : w1;
    else if (jp)       nv = (j == k0) ? -__fmaf_rn(c0, q00, c1 * q10)
                                      : -__fmaf_rn(c0, q01, c1 * q11);
    else               nv = v - __fmaf_rn(c0, w0, c1 * w1);
    return nv;
}

__device__ __forceinline__ void gj16b(float (*M)[17], float (*rb)[2][DX],
                                      float (*cb)[2][DX], float (*spv)[4],
                                      int i, int j) {
    #pragma unroll
    for (int s = 0; s < 8; ++s) {
        const int nx = (s & 1) ^ 1;
        const int k0 = 2 * s;
        float nv = gj_stage(M, rb, cb, spv, i, j, s);
        M[i][j] = nv;
        if (s < 7) {
            if (i == k0 + 2) rb[nx][0][j] = nv;
            if (i == k0 + 3) rb[nx][1][j] = nv;
            if (j == k0 + 2) cb[nx][0][i] = nv;
            if (j == k0 + 3) cb[nx][1][i] = nv;
            if ((i == k0 + 2 || i == k0 + 3) && (j == k0 + 2 || j == k0 + 3))
                spv[nx][(i - k0 - 2) * 2 + (j - k0 - 2)] = nv;
        }
        __syncthreads();
    }
}

__global__ void k_scan(const float* __restrict__ gmask) {
    int idx = blockIdx.x * 256 + threadIdx.x;
    int bad = (gmask[idx] != 1.0f) ? 1 : 0;
    int any = __syncthreads_or(bad);
    if (threadIdx.x == 0) g_bad[blockIdx.x] = any;
}

// ---------------- K1: shared Riccati (single inversion, 12 syncs) -----------
__global__ __launch_bounds__(256, 1)
void k1_riccati(const float* __restrict__ gA, const float* __restrict__ gC,
                const float* __restrict__ gLam0, const float* __restrict__ gWlog,
                const float* __restrict__ gRlog) {
    __shared__ float sA[DX][17], sS[DX][17], sC[DA][17];
    __shared__ float sCtRinv[DX][33], sK[DX][33];
    __shared__ float sM[DX][17], sT[DX][17], sP[DX][17], sLam[DX][17];
    __shared__ float rb[2][2][DX], cb[2][2][DX], spv[2][4];
    __shared__ float s_rinv[DA], sW[DX];

    const int tid = threadIdx.x;
    const int i = tid >> 4, j = tid & 15;

    {
        int bad = 0;
        #pragma unroll
        for (int r = 0; r < 4; ++r) bad |= g_bad[tid + r * 256];
        int any = __syncthreads_or(bad);
        if (any) { if (tid == 0) { g_allones = 0; g_tc = 0; } return; }
    }

    sA[i][j] = gA[tid];
    for (int idx = tid; idx < DA * DX; idx += 256) sC[idx >> 4][idx & 15] = gC[idx];
    if (tid < DA) s_rinv[tid] = __expf(-gRlog[tid]);
    if (tid < DX) sW[tid] = __expf(gWlog[tid]);
    sP[i][j] = gLam0[tid];
    __syncthreads();
    for (int idx = tid; idx < DX * DA; idx += 256) {
        int x = idx >> 5, aa = idx & 31;
        sCtRinv[x][aa] = sC[aa][x] * s_rinv[aa];
    }
    __syncthreads();
    {
        float acc = 0.f;
        #pragma unroll
        for (int aa = 0; aa < DA; ++aa) acc = fmaf(sCtRinv[i][aa], sC[aa][j], acc);
        sS[i][j] = acc;   // S = C^T R^-1 C
    }
    __syncthreads();

    int tcv = -1;
    for (int t = 0; t < TC; ++t) {
        // p0: X = I + P S, prime GJ
        {
            float x = (i == j) ? 1.f : 0.f;
            #pragma unroll
            for (int k = 0; k < DX; ++k) x = fmaf(sP[i][k], sS[k][j], x);
            sM[i][j] = x;
            if (i < 2) rb[0][i][j] = x;
            if (j < 2) cb[0][j][i] = x;
            if (i < 2 && j < 2) spv[0][i * 2 + j] = x;
        }
        __syncthreads();
        gj16b(sM, rb, cb, spv, i, j);             // sM = X^-1   [8 syncs]
        // p1: Lam = X^-1 P
        {
            float acc = 0.f;
            #pragma unroll
            for (int k = 0; k < DX; ++k) acc = fmaf(sM[i][k], sP[k][j], acc);
            sLam[i][j] = acc;
            g_Lt[t][tid] = acc;
        }
        __syncthreads();
        // p2: K = Lam CtRinv (store); T = A Lam; G = I - Lam S (store)
        {
            #pragma unroll
            for (int rep = 0; rep < 2; ++rep) {
                int idx = tid + rep * 256;
                int ri = idx >> 5, ca = idx & 31;
                float acc = 0.f;
                #pragma unroll
                for (int y = 0; y < DX; ++y) acc = fmaf(sLam[ri][y], sCtRinv[y][ca], acc);
                sK[ri][ca] = acc;
                g_Kt[t][ri][ca] = acc;
            }
            float acc = 0.f, ls = 0.f;
            #pragma unroll
            for (int k = 0; k < DX; ++k) {
                acc = fmaf(sA[i][k], sLam[k][j], acc);
                ls  = fmaf(sLam[i][k], sS[k][j], ls);
            }
            sT[i][j] = acc;
            g_Gt[t][i][j] = ((i == j) ? 1.f : 0.f) - ls;
        }
        __syncthreads();
        // p3: M = A - T S ; N = A K ; P' = T A^T + W ; convergence
        int pred;
        {
            float ts = 0.f;
            #pragma unroll
            for (int k = 0; k < DX; ++k) ts = fmaf(sT[i][k], sS[k][j], ts);
            g_Mt[t][i][j] = sA[i][j] - ts;
            #pragma unroll
            for (int rep = 0; rep < 2; ++rep) {
                int idx = tid + rep * 256;
                int ri = idx >> 5, ca = idx & 31;
                float acc = 0.f;
                #pragma unroll
                for (int y = 0; y < DX; ++y) acc = fmaf(sA[ri][y], sK[y][ca], acc);
                g_Nt[t][ri][ca] = acc;
            }
            float pn = (i == j) ? sW[i] : 0.f;
            #pragma unroll
            for (int k = 0; k < DX; ++k) pn = fmaf(sT[i][k], sA[j][k], pn);
            g_Lp[t][tid] = pn;
            pred = (fabsf(pn - sP[i][j]) > 1e-6f) ? 1 : 0;
            sP[i][j] = pn;
        }
        int notconv = __syncthreads_or(pred);
        if (!notconv) { tcv = t; break; }
    }
    if (tid == 0) {
        if (tcv < 0) { g_allones = 0; g_tc = 0; }
        else { g_allones = 1; g_tc = tcv; }
    }
}

// ---------------- K2: d/f precompute + Lambda streaming (64 t/CTA) ----------
__global__ __launch_bounds__(256, 4)
void k2_dfl(const float* __restrict__ ga, const float* __restrict__ gu,
            const float* __restrict__ gB, float* __restrict__ out) {
    if (!g_allones) return;
    const int tc = g_tc;
    const int b = blockIdx.x >> 4;
    const int t0 = (blockIdx.x & 15) << 6;
    const int tid = threadIdx.x;
    const int w = tid >> 5, l = tid & 31;
    const int i = l & 15, h = l >> 4;

    __shared__ __align__(16) float s_a[64 * 32];
    __shared__ __align__(16) float s_u[64 * 16];
    __shared__ __align__(16) float sLp[256], sLt[256];

    {
        const float4* src = (const float4*)(ga + ((size_t)b * T_STEPS + t0) * DA);
        float4* dst = (float4*)s_a;
        dst[tid] = src[tid];
        dst[tid + 256] = src[tid + 256];
        const float4* srcu = (const float4*)(gu + ((size_t)b * T_STEPS + t0) * DX);
        ((float4*)s_u)[tid] = srcu[tid];
    }
    sLp[tid] = g_Lp[tc][tid];
    sLt[tid] = g_Lt[tc][tid];

    float Np[16], Kp[16], Bp[8];
    #pragma unroll
    for (int c = 0; c < 16; ++c) {
        Np[c] = g_Nt[tc][i][16 * h + c];
        Kp[c] = g_Kt[tc][i][16 * h + c];
    }
    #pragma unroll
    for (int c = 0; c < 8; ++c) Bp[c] = gB[i * 16 + 8 * h + c];
    __syncthreads();

    const int e4c = tid & 63;
    const float4 vps = ((const float4*)sLp)[e4c];
    const float4 vls = ((const float4*)sLt)[e4c];
    #pragma unroll
    for (int it = 0; it < 16; ++it) {
        const int q = tid + it * 256;
        const int tt = t0 + (q >> 6);
        float4 vp, vl;
        if (tt >= tc) { vp = vps; vl = vls; }
        else {
            vp = ((const float4*)g_Lp[tt])[e4c];
            vl = ((const float4*)g_Lt[tt])[e4c];
        }
        size_t off = ((size_t)tt * NB + b) * 256 + (size_t)e4c * 4;
        __stcs((float4*)(out + BASE_LP + off), vp);
        __stcs((float4*)(out + BASE_LT + off), vl);
    }

    #pragma unroll
    for (int it = 0; it < 8; ++it) {
        const int t = t0 + w + 8 * it;
        const int tl = t - t0;
        float d = 0.f, f = 0.f;
        if (t >= tc) {
            #pragma unroll
            for (int c = 0; c < 16; ++c) {
                float av = s_a[tl * 32 + 16 * h + c];
                d = fmaf(Np[c], av, d);
                f = fmaf(Kp[c], av, f);
            }
        } else {
            #pragma unroll
            for (int c = 0; c < 16; ++c) {
                float av = s_a[tl * 32 + 16 * h + c];
                d = fmaf(__ldg(&g_Nt[t][i][16 * h + c]), av, d);
                f = fmaf(__ldg(&g_Kt[t][i][16 * h + c]), av, f);
            }
        }
        if (t != T_STEPS - 1) {
            #pragma unroll
            for (int c = 0; c < 8; ++c)
                d = fmaf(Bp[c], s_u[tl * 16 + 8 * h + c], d);
        }
        d += __shfl_xor_sync(0xffffffffu, d, 16);
        f += __shfl_xor_sync(0xffffffffu, f, 16);
        if (h == 0) g_df[0][b][t][i] = d;
        else        g_df[1][b][t][i] = f;
    }
}

// ---------------- K3: affine mu recursion, 16 chunks of 64 per seq ----------
__global__ __launch_bounds__(256, 2)
void k3_mu(const float* __restrict__ gmu0, float* __restrict__ out) {
    if (!g_allones) return;
    const int tc = g_tc;
    const int b = blockIdx.x >> 1;
    const int chunk = ((blockIdx.x & 1) << 3) | (threadIdx.x >> 5);
    const int lane = threadIdx.x & 31, r = lane & 15;
    const int cs = chunk << 6, ce = cs + 64;
    const int s = (chunk == 0) ? 0 : cs - 64;   // 64-step burn-in

    float cst[16];
    {
        const float (*CF)[17] = (lane < 16) ? g_Mt[tc] : g_Gt[tc];
        #pragma unroll
        for (int k = 0; k < DX; ++k) cst[k] = CF[r][k];
    }
    const float* dfb = (lane < 16) ? &g_df[0][b][0][r] : &g_df[1][b][0][r];
    float mu = (chunk == 0 && lane < 16) ? __ldg(&gmu0[r]) : 0.f;

    auto ld = [&](int t) { return __ldg(dfb + (size_t)t * DX); };
    auto body = [&](int t, const float* cf, float val) {
        float a0 = 0.f, a1 = 0.f, a2 = 0.f, a3 = 0.f;
        #pragma unroll
        for (int k = 0; k < DX; k += 4) {
            a0 = fmaf(cf[k],     __shfl_sync(0xffffffffu, mu, k),     a0);
            a1 = fmaf(cf[k + 1], __shfl_sync(0xffffffffu, mu, k + 1), a1);
            a2 = fmaf(cf[k + 2], __shfl_sync(0xffffffffu, mu, k + 2), a2);
            a3 = fmaf(cf[k + 3], __shfl_sync(0xffffffffu, mu, k + 3), a3);
        }
        float res = ((a0 + a1) + (a2 + a3)) + val;
        if (t >= cs)
            out[((lane < 16) ? BASE_MP : BASE_MT) + ((size_t)t * NB + b) * DX + r] = res;
        mu = res;
    };
    auto dostep = [&](int t, float val) {
        if (t < tc) {
            float cf[16];
            const float (*CF)[17] = (lane < 16) ? g_Mt[t] : g_Gt[t];
            #pragma unroll
            for (int k = 0; k < DX; ++k) cf[k] = __ldg(&CF[r][k]);
            body(t, cf, val);
        } else {
            body(t, cst, val);
        }
    };

    // 8-deep software pipeline on the d/f loads
    float v[8];
    int t = s;
    #pragma unroll
    for (int q = 0; q < 8; ++q) v[q] = ld(t + q);
    for (; t < ce; t += 8) {
        #pragma unroll
        for (int q = 0; q < 8; ++q) {
            dostep(t + q, v[q]);
            v[q] = (t + q + 8 < ce) ? ld(t + q + 8) : 0.f;
        }
    }
}

// ---------------- Fallback: full general-mask kernel (guarded) ----------
__global__ __launch_bounds__(256, 2)
void ldm_fallback(const float* __restrict__ ga, const float* __restrict__ gu,
                  const float* __restrict__ gmask, const float* __restrict__ gA,
                  const float* __restrict__ gB, const float* __restrict__ gC,
                  const float* __restrict__ gmu0, const float* __restrict__ gLam0,
                  const float* __restrict__ gWlog, const float* __restrict__ gRlog,
                  float* __restrict__ out) {
    if (g_allones) return;
    __shared__ float sA[DX][17], sB[DX][17], sCtRinvC[DX][17];
    __shared__ float sC[DA][17];
    __shared__ float sCtRinv[DX][33], sK[DX][33];
    __shared__ float sM[DX][17], sT[DX][17], sLt[DX][17], sKC[DX][17];
    __shared__ float sP[2][DX][17];
    __shared__ float rb[2][2][DX], cb[2][2][DX], spv[2][4];
    __shared__ float s_rinv[DA], sW[DX];
    __shared__ float s_mu[DX], s_mut[DX], s_r[DA], s_u[DX];
    __shared__ __align__(16) float sPflat[256];
    __shared__ __align__(16) float sLtflat[256];
    __shared__ float s_mask[T_STEPS];
    __shared__ int sFlag;
    __shared__ int sLastMasked;

    const int tid = threadIdx.x;
    const int i = tid >> 4, j = tid & 15;
    const int b = blockIdx.x;

    if (tid == 0) sLastMasked = -1;
    __syncthreads();
    sA[i][j] = gA[tid];
    sB[i][j] = gB[tid];
    for (int idx = tid; idx < DA * DX; idx += 256) sC[idx >> 4][idx & 15] = gC[idx];
    if (tid < DA) s_rinv[tid] = __expf(-gRlog[tid]);
    if (tid < DX) { sW[tid] = __expf(gWlog[tid]); s_mu[tid] = gmu0[tid]; }
    sP[0][i][j] = gLam0[tid];
    #pragma unroll
    for (int rep = 0; rep < T_STEPS / 256; ++rep) {
        int idx = tid + rep * 256;
        float mv = gmask[(size_t)b * T_STEPS + idx];
        s_mask[idx] = mv;
        if (mv != 1.0f) atomicMax(&sLastMasked, idx);
    }
    __syncthreads();
    for (int idx = tid; idx < DX * DA; idx += 256) {
        int x = idx >> 5, aa = idx & 31;
        sCtRinv[x][aa] = sC[aa][x] * s_rinv[aa];
    }
    __syncthreads();
    {
        float acc = 0.f;
        #pragma unroll
        for (int aa = 0; aa < DA; ++aa) acc = fmaf(sCtRinv[i][aa], sC[aa][j], acc);
        sCtRinvC[i][j] = acc;
    }
    __syncthreads();

    int cur = 0;
    int t_frozen = T_STEPS;
    const int lastMasked = sLastMasked;

    for (int t = 0; t < T_STEPS; ++t) {
        if (tid == 0) sFlag = 0;
        const float m = s_mask[t];
        const bool m1 = (m == 1.0f);
        float rga = 0.f, rgu = 0.f;
        if (tid < DA) {
            rga = __ldg(&ga[((size_t)b * T_STEPS + t) * DA + tid]);
        } else if (tid < DA + DX) {
            rgu = (t == T_STEPS - 1) ? 0.f
                : __ldg(&gu[((size_t)b * T_STEPS + t) * DX + (tid - DA)]);
        }
        {
            float v = sP[cur][i][j];
            sM[i][j] = v;
            if (i < 2) rb[0][i][j] = v;
            if (j < 2) cb[0][j][i] = v;
            if (i < 2 && j < 2) spv[0][i * 2 + j] = v;
        }
        __syncthreads();
        gj16b(sM, rb, cb, spv, i, j);
        {
            float nv = sM[i][j] + sCtRinvC[i][j];
            sM[i][j] = nv;
            if (i < 2) rb[0][i][j] = nv;
            if (j < 2) cb[0][j][i] = nv;
            if (i < 2 && j < 2) spv[0][i * 2 + j] = nv;
        }
        __syncthreads();
        gj16b(sM, rb, cb, spv, i, j);
        {
            #pragma unroll
            for (int rep = 0; rep < 2; ++rep) {
                int idx = tid + rep * 256;
                int ri = idx >> 5, ca = idx & 31;
                float acc = 0.f;
                #pragma unroll
                for (int y = 0; y < DX; ++y) acc = fmaf(sM[ri][y], sCtRinv[y][ca], acc);
                sK[ri][ca] = acc;
            }
            float acc = 0.f;
            #pragma unroll
            for (int k = 0; k < DX; ++k) acc = fmaf(sA[i][k], sM[k][j], acc);
            sT[i][j] = acc;
            if (m1) sLt[i][j] = sM[i][j];
        }
        __syncthreads();
        if (!m1) {
            float acc = 0.f;
            #pragma unroll
            for (int aa = 0; aa < DA; ++aa) acc = fmaf(sK[i][aa], sC[aa][j], acc);
            sKC[i][j] = acc;
            __syncthreads();
            float acc2 = 0.f;
            #pragma unroll
            for (int k = 0; k < DX; ++k) acc2 = fmaf(sKC[i][k], sP[cur][k][j], acc2);
            sLt[i][j] = sP[cur][i][j] - m * acc2;
            __syncthreads();
            float acc3 = 0.f;
            #pragma unroll
            for (int k = 0; k < DX; ++k) acc3 = fmaf(sA[i][k], sLt[k][j], acc3);
            sT[i][j] = acc3;
            __syncthreads();
        }
        const int nxt = cur ^ 1;
        {
            float acc = (i == j) ? sW[i] : 0.f;
            #pragma unroll
            for (int k = 0; k < DX; ++k) acc = fmaf(sT[i][k], sA[j][k], acc);
            sP[nxt][i][j] = acc;
            if (fabsf(acc - sP[cur][i][j]) > 1e-6f) sFlag = 1;
            size_t off = ((size_t)t * NB + b) * 256 + tid;
            out[BASE_LP + off] = acc;
            out[BASE_LT + off] = sLt[i][j];
            if (tid < DA) {
                float ap = 0.f;
                #pragma unroll
                for (int k = 0; k < DX; ++k) ap = fmaf(sC[tid][k], s_mu[k], ap);
                s_r[tid] = fmaf(m, rga, -ap);
            } else if (tid < DA + DX) {
                s_u[tid - DA] = rgu;
            }
        }
        __syncthreads();
        if (tid < DX) {
            float acc = 0.f;
            #pragma unroll
            for (int aa = 0; aa < DA; ++aa) acc = fmaf(sK[tid][aa], s_r[aa], acc);
            float mt = s_mu[tid] + m * acc;
            s_mut[tid] = mt;
            out[BASE_MT + ((size_t)t * NB + b) * DX + tid] = mt;
        }
        __syncthreads();
        if (tid < DX) {
            float acc = 0.f;
            #pragma unroll
            for (int k = 0; k < DX; ++k) acc = fmaf(sA[tid][k], s_mut[k], acc);
            #pragma unroll
            for (int k = 0; k < DX; ++k) acc = fmaf(sB[tid][k], s_u[k], acc);
            s_mu[tid] = acc;
            out[BASE_MP + ((size_t)t * NB + b) * DX + tid] = acc;
        }
        const bool conv = m1 && (sFlag == 0) && (t >= lastMasked);
        __syncthreads();
        cur = nxt;
        if (conv) { t_frozen = t; break; }
    }

    if (t_frozen < T_STEPS) {
        sPflat[tid]  = sP[cur][i][j];
        sLtflat[tid] = sLt[i][j];
        __syncthreads();
        const int warp = tid >> 5, lane = tid & 31, lr = lane & 15;
        const int t0f = t_frozen + 1;
        const int n = T_STEPS - t0f;
        const int L = (n + 7) / 8;
        const int cs = t0f + warp * L;
        const int ce = min(cs + L, T_STEPS);
        const int tb = (warp == 0) ? t0f : cs - L;
        const float4* pf = (const float4*)sPflat;
        const float4* lf = (const float4*)sLtflat;
        const float4 p0 = pf[2 * lane], p1 = pf[2 * lane + 1];
        const float4 l0 = lf[2 * lane], l1 = lf[2 * lane + 1];
        int tt = t0f + warp;
        float Crow[DX], Krow[DA];
        #pragma unroll
        for (int k = 0; k < DX; ++k) Crow[k] = sC[lane][k];
        #pragma unroll
        for (int aa = 0; aa < DA; ++aa) Krow[aa] = sK[lr][aa];
        float mu = (warp == 0) ? s_mu[lr] : 0.f;
        for (int t = tb; t < ce; ++t) {
            const float m = s_mask[t];
            const float av = __ldg(&ga[((size_t)b * T_STEPS + t) * DA + lane]);
            const float uv = (lane < DX && t < T_STEPS - 1)
                ? __ldg(&gu[((size_t)b * T_STEPS + t) * DX + lane]) : 0.f;
            if (tt < T_STEPS) {
                size_t off = ((size_t)tt * NB + b) * 256 + lane * 8;
                float4* o1 = (float4*)(out + BASE_LP + off);
                o1[0] = p0; o1[1] = p1;
                float4* o2 = (float4*)(out + BASE_LT + off);
                o2[0] = l0; o2[1] = l1;
                tt += 8;
            }
            float ap0 = 0.f, ap1 = 0.f;
            #pragma unroll
            for (int k = 0; k < DX; k += 2) {
                ap0 = fmaf(Crow[k],     __shfl_sync(0xffffffffu, mu, k),     ap0);
                ap1 = fmaf(Crow[k + 1], __shfl_sync(0xffffffffu, mu, k + 1), ap1);
            }
            const float r = fmaf(m, av, -(ap0 + ap1));
            float g0 = 0.f, g1 = 0.f, g2 = 0.f, g3 = 0.f;
            #pragma unroll
            for (int aa = 0; aa < DA; aa += 4) {
                g0 = fmaf(Krow[aa],     __shfl_sync(0xffffffffu, r, aa),     g0);
                g1 = fmaf(Krow[aa + 1], __shfl_sync(0xffffffffu, r, aa + 1), g1);
                g2 = fmaf(Krow[aa + 2], __shfl_sync(0xffffffffu, r, aa + 2), g2);
                g3 = fmaf(Krow[aa + 3], __shfl_sync(0xffffffffu, r, aa + 3), g3);
            }
            const float mt = fmaf(m, (g0 + g1) + (g2 + g3), mu);
            float mun = 0.f;
            #pragma unroll
            for (int k = 0; k < DX; ++k) {
                mun = fmaf(sA[lr][k], __shfl_sync(0xffffffffu, mt, k), mun);
                mun = fmaf(sB[lr][k], __shfl_sync(0xffffffffu, uv, k), mun);
            }
            if (t >= cs && lane < DX) {
                out[BASE_MT + ((size_t)t * NB + b) * DX + lane] = mt;
                out[BASE_MP + ((size_t)t * NB + b) * DX + lane] = mun;
            }
            mu = mun;
        }
        for (; tt < T_STEPS; tt += 8) {
            size_t off = ((size_t)tt * NB + b) * 256 + lane * 8;
            float4* o1 = (float4*)(out + BASE_LP + off);
            o1[0] = p0; o1[1] = p1;
            float4* o2 = (float4*)(out + BASE_LT + off);
            o2[0] = l0; o2[1] = l1;
        }
    }
}

extern "C" void kernel_launch(void* const* d_in, const int* in_sizes, int n_in,
                              void* d_out, int out_size) {
    (void)in_sizes; (void)n_in; (void)out_size;
    const float* ga    = (const float*)d_in[0];
    const float* gu    = (const float*)d_in[1];
    const float* gmask = (const float*)d_in[2];
    const float* gA    = (const float*)d_in[3];
    const float* gB    = (const float*)d_in[4];
    const float* gC    = (const float*)d_in[5];
    const float* gmu0  = (const float*)d_in[6];
    const float* gLam0 = (const float*)d_in[7];
    const float* gWlog = (const float*)d_in[8];
    const float* gRlog = (const float*)d_in[9];
    float* out = (float*)d_out;

    k_scan<<<1024, 256>>>(gmask);
    k1_riccati<<<1, 256>>>(gA, gC, gLam0, gWlog, gRlog);
    k2_dfl<<<NB * 16, 256>>>(ga, gu, gB, out);
    k3_mu<<<NB * 2, 256>>>(gmu0, out);
    ldm_fallback<<<NB, 256>>>(ga, gu, gmask, gA, gB, gC, gmu0, gLam0,
                              gWlog, gRlog, out);
}